// round 2
// baseline (speedup 1.0000x reference)
#include <cuda_runtime.h>
#include <math.h>
#include <stdint.h>

#define NB 2
#define NC 64
#define NH 48
#define NW 48
#define HW 2304
#define INNER 64
#define HEADS 8
#define DH 8
#define MM 36
#define SCALE 0.35355339059327373f

// ---------------- scratch (device globals; no allocation allowed) ----------------
__device__ float g_qt[NB * HW * INNER];          // q channel-last: [b][p][c]
__device__ float g_kt[NB * HW * INNER];          // k channel-last: [b][p][c]
__device__ float g_vt[NB * HEADS * HW * DH];     // v: [b][head][j][c8]
__device__ float g_qd[NB * INNER * MM];          // conv+gelu(q): [b][oc][pos36]
__device__ float g_kd[NB * INNER * MM];
__device__ float g_dots[NB * HEADS * MM * MM];   // [b][head][i36][j36]

// ---------------- kernel A: 1x1 conv qkv + layout transforms ----------------
// grid: 2 b * 36 ptiles(64) = 72 blocks, 256 threads
__global__ void qkv_kernel(const float* __restrict__ f, const float* __restrict__ wqkv) {
    __shared__ float sF[64 * 64];   // [c][pp]
    int b = blockIdx.x / 36;
    int p0 = (blockIdx.x % 36) * 64;

    for (int idx = threadIdx.x; idx < 64 * 64; idx += 256) {
        int c = idx >> 6, pp = idx & 63;
        sF[idx] = f[(b * 64 + c) * HW + p0 + pp];
    }
    __syncthreads();

    int pp = threadIdx.x & 63;
    int o0 = threadIdx.x >> 6;   // 0..3
    int p = p0 + pp;
    for (int o = o0; o < 192; o += 4) {
        float acc = 0.f;
        const float* wr = wqkv + o * 64;
        #pragma unroll 16
        for (int c = 0; c < 64; c++) acc = fmaf(__ldg(&wr[c]), sF[c * 64 + pp], acc);
        if (o < 64) {
            g_qt[(b * HW + p) * 64 + o] = acc;
        } else if (o < 128) {
            g_kt[(b * HW + p) * 64 + (o - 64)] = acc;
        } else {
            int oi = o - 128;
            g_vt[(((b * HEADS) + (oi >> 3)) * HW + p) * DH + (oi & 7)] = acc;
        }
    }
}

// ---------------- kernel B: 11x11 stride-8 pad-2 conv + exact GELU ----------------
// grid: 2 tensors * 2 b * 64 oc = 256 blocks, 128 threads (4 warps, 9 outputs each)
__global__ void conv_kernel(const float* __restrict__ wq, const float* __restrict__ bq,
                            const float* __restrict__ wk, const float* __restrict__ bk) {
    int bid = blockIdx.x;
    int t  = bid >> 7;
    int b  = (bid >> 6) & 1;
    int oc = bid & 63;

    const float* wsrc = (t ? wk : wq) + oc * 64 * 121;
    const float* in   = (t ? g_kt : g_qt) + b * HW * 64;

    __shared__ float sw[121 * 64];   // [tap][ic]
    for (int idx = threadIdx.x; idx < 121 * 64; idx += 128) {
        int tap = idx >> 6, ic = idx & 63;
        sw[idx] = wsrc[ic * 121 + tap];
    }
    __syncthreads();

    int warp = threadIdx.x >> 5, lane = threadIdx.x & 31;
    for (int pos = warp * 9; pos < warp * 9 + 9; pos++) {
        int oh = pos / 6, ow = pos % 6;
        int ihb = oh * 8 - 2, iwb = ow * 8 - 2;
        float acc = 0.f;
        #pragma unroll
        for (int kh = 0; kh < 11; kh++) {
            int ih = ihb + kh;
            if ((unsigned)ih >= 48u) continue;
            #pragma unroll
            for (int kw = 0; kw < 11; kw++) {
                int iw = iwb + kw;
                if ((unsigned)iw >= 48u) continue;
                const float* ip = in + (ih * 48 + iw) * 64;
                const float* wp = sw + (kh * 11 + kw) * 64;
                acc = fmaf(ip[lane], wp[lane], acc);
                acc = fmaf(ip[lane + 32], wp[lane + 32], acc);
            }
        }
        #pragma unroll
        for (int off = 16; off; off >>= 1)
            acc += __shfl_xor_sync(0xffffffffu, acc, off);
        if (lane == 0) {
            float x = acc + (t ? bk : bq)[oc];
            float g = 0.5f * x * (1.0f + erff(x * 0.7071067811865476f));
            (t ? g_kd : g_qd)[(b * 64 + oc) * MM + pos] = g;
        }
    }
}

// ---------------- kernel C: dots[b,h,i36,j36] ----------------
__global__ void dots_kernel() {
    int idx = blockIdx.x * 256 + threadIdx.x;
    if (idx >= NB * HEADS * MM * MM) return;
    int j  = idx % 36;
    int i  = (idx / 36) % 36;
    int bh = idx / (36 * 36);
    int b = bh >> 3, hd = bh & 7;
    const float* qd = g_qd + (b * 64 + hd * 8) * MM;
    const float* kd = g_kd + (b * 64 + hd * 8) * MM;
    float s = 0.f;
    #pragma unroll
    for (int c = 0; c < 8; c++) s = fmaf(qd[c * MM + i], kd[c * MM + j], s);
    g_dots[idx] = s * SCALE;
}

// ---------------- kernel D: fused pos-logits + softmax + attn@v ----------------
// one warp per output row; grid 4608 blocks * 256 threads (8 warps)
__global__ void attn_kernel(const float* __restrict__ pos_h, const float* __restrict__ pos_w,
                            float* __restrict__ out) {
    __shared__ float sh[8][144];   // per warp: [0..35]=D, [48..95]=A, [96..143]=B
    int warp = threadIdx.x >> 5, lane = threadIdx.x & 31;
    int row = blockIdx.x * 8 + warp;            // < 36864
    int b  = row / (HEADS * HW);
    int hd = (row / HW) & 7;
    int i  = row % HW;

    // q_i[0..7] : contiguous 8 floats in channel-last layout
    const float4* qb = (const float4*)(g_qt + ((size_t)(b * HW + i)) * 64 + hd * 8);
    float4 q0 = qb[0], q1 = qb[1];
    float qc[8] = {q0.x, q0.y, q0.z, q0.w, q1.x, q1.y, q1.z, q1.w};

    float* sD = sh[warp];
    float* sA = sh[warp] + 48;
    float* sB = sh[warp] + 96;

    for (int jh = lane; jh < 48; jh += 32) {
        float a = 0.f, bb = 0.f;
        #pragma unroll
        for (int c = 0; c < 8; c++) {
            a  = fmaf(qc[c], pos_h[c * 48 + jh], a);
            bb = fmaf(qc[c], pos_w[c * 48 + jh], bb);
        }
        sA[jh] = a;
        sB[jh] = bb;
    }
    {
        const float* dsrc = g_dots + ((b * HEADS + hd) * MM + (i >> 6)) * MM;
        for (int t2 = lane; t2 < 36; t2 += 32)
            sD[t2] = dsrc[t2];
    }
    __syncwarp();

    // separable upper bound on row max (softmax shift-invariant)
    float mA = -1e30f, mB = -1e30f, mD = -1e30f;
    for (int t2 = lane; t2 < 48; t2 += 32) {
        mA = fmaxf(mA, sA[t2]);
        mB = fmaxf(mB, sB[t2]);
    }
    for (int t2 = lane; t2 < 36; t2 += 32)
        mD = fmaxf(mD, sD[t2]);
    #pragma unroll
    for (int off = 16; off; off >>= 1) {
        mA = fmaxf(mA, __shfl_xor_sync(0xffffffffu, mA, off));
        mB = fmaxf(mB, __shfl_xor_sync(0xffffffffu, mB, off));
        mD = fmaxf(mD, __shfl_xor_sync(0xffffffffu, mD, off));
    }
    float M = mA + mB + mD;

    const float4* vb = (const float4*)(g_vt + ((size_t)(b * HEADS + hd)) * HW * DH);
    float ssum = 0.f;
    float a0 = 0.f, a1 = 0.f, a2 = 0.f, a3 = 0.f, a4 = 0.f, a5 = 0.f, a6 = 0.f, a7 = 0.f;
    int jh = 0, jw = lane;   // j = lane < 48 initially
    for (int j = lane; j < HW; j += 32) {
        float s = sD[j >> 6] + sA[jh] + sB[jw];
        float p = __expf(s - M);
        ssum += p;
        float4 v0 = vb[2 * j];
        float4 v1 = vb[2 * j + 1];
        a0 = fmaf(p, v0.x, a0); a1 = fmaf(p, v0.y, a1);
        a2 = fmaf(p, v0.z, a2); a3 = fmaf(p, v0.w, a3);
        a4 = fmaf(p, v1.x, a4); a5 = fmaf(p, v1.y, a5);
        a6 = fmaf(p, v1.z, a6); a7 = fmaf(p, v1.w, a7);
        jw += 32;
        if (jw >= 48) { jw -= 48; jh++; }
    }

    #pragma unroll
    for (int off = 16; off; off >>= 1) {
        ssum += __shfl_xor_sync(0xffffffffu, ssum, off);
        a0 += __shfl_xor_sync(0xffffffffu, a0, off);
        a1 += __shfl_xor_sync(0xffffffffu, a1, off);
        a2 += __shfl_xor_sync(0xffffffffu, a2, off);
        a3 += __shfl_xor_sync(0xffffffffu, a3, off);
        a4 += __shfl_xor_sync(0xffffffffu, a4, off);
        a5 += __shfl_xor_sync(0xffffffffu, a5, off);
        a6 += __shfl_xor_sync(0xffffffffu, a6, off);
        a7 += __shfl_xor_sync(0xffffffffu, a7, off);
    }

    float inv = 1.0f / ssum;
    float r = a0;
    if (lane == 1) r = a1;
    if (lane == 2) r = a2;
    if (lane == 3) r = a3;
    if (lane == 4) r = a4;
    if (lane == 5) r = a5;
    if (lane == 6) r = a6;
    if (lane == 7) r = a7;
    if (lane < 8)
        out[((size_t)(b * 64) + hd * 8 + lane) * HW + i] = r * inv;
}

// ---------------- launch ----------------
extern "C" void kernel_launch(void* const* d_in, const int* in_sizes, int n_in,
                              void* d_out, int out_size) {
    const float* f    = (const float*)d_in[0];
    const float* wqkv = (const float*)d_in[1];
    const float* wq   = (const float*)d_in[2];
    const float* bq   = (const float*)d_in[3];
    const float* wk   = (const float*)d_in[4];
    const float* bk   = (const float*)d_in[5];
    const float* ph   = (const float*)d_in[6];
    const float* pw   = (const float*)d_in[7];
    float* out = (float*)d_out;

    qkv_kernel<<<72, 256>>>(f, wqkv);
    conv_kernel<<<256, 128>>>(wq, bq, wk, bk);
    dots_kernel<<<81, 256>>>();
    attn_kernel<<<4608, 256>>>(ph, pw, out);
}

// round 3
// speedup vs baseline: 3.3542x; 3.3542x over previous
#include <cuda_runtime.h>
#include <math.h>
#include <stdint.h>

#define NB 2
#define NC 64
#define NH 48
#define NW 48
#define HW 2304
#define INNER 64
#define HEADS 8
#define DH 8
#define MM 36
#define SCALE 0.35355339059327373f

// ---------------- scratch (device globals; no allocation allowed) ----------------
__device__ float g_qt[NB * HW * INNER];          // q channel-last: [b][p][c]
__device__ float g_kt[NB * HW * INNER];          // k channel-last: [b][p][c]
__device__ float4 g_vlo4[NB * HEADS * HW];       // v channels 0..3:  [b][head][j]
__device__ float4 g_vhi4[NB * HEADS * HW];       // v channels 4..7
__device__ float g_qd[NB * INNER * MM];          // conv+gelu(q): [b][oc][pos36]
__device__ float g_kd[NB * INNER * MM];
__device__ float g_dots[NB * HEADS * MM * MM];   // [b][head][i36][j36]

// ---------------- kernel A: 1x1 conv qkv + layout transforms ----------------
// grid: 2 b * 36 ptiles(64) = 72 blocks, 256 threads
__global__ void qkv_kernel(const float* __restrict__ f, const float* __restrict__ wqkv) {
    __shared__ float sF[64 * 64];   // [c][pp]
    int b = blockIdx.x / 36;
    int p0 = (blockIdx.x % 36) * 64;

    for (int idx = threadIdx.x; idx < 64 * 64; idx += 256) {
        int c = idx >> 6, pp = idx & 63;
        sF[idx] = f[(b * 64 + c) * HW + p0 + pp];
    }
    __syncthreads();

    int pp = threadIdx.x & 63;
    int o0 = threadIdx.x >> 6;   // 0..3
    int p = p0 + pp;
    for (int o = o0; o < 192; o += 4) {
        const float* wr = wqkv + o * 64;
        float a0 = 0.f, a1 = 0.f, a2 = 0.f, a3 = 0.f;
        #pragma unroll
        for (int c = 0; c < 16; c++) {
            a0 = fmaf(__ldg(&wr[c]),      sF[c * 64 + pp],        a0);
            a1 = fmaf(__ldg(&wr[c + 16]), sF[(c + 16) * 64 + pp], a1);
            a2 = fmaf(__ldg(&wr[c + 32]), sF[(c + 32) * 64 + pp], a2);
            a3 = fmaf(__ldg(&wr[c + 48]), sF[(c + 48) * 64 + pp], a3);
        }
        float acc = (a0 + a1) + (a2 + a3);
        if (o < 64) {
            g_qt[(b * HW + p) * 64 + o] = acc;
        } else if (o < 128) {
            g_kt[(b * HW + p) * 64 + (o - 64)] = acc;
        } else {
            int oi = o - 128;
            int hd = oi >> 3, c = oi & 7;
            float* vout = (float*)(c < 4 ? g_vlo4 : g_vhi4);
            vout[((size_t)(b * HEADS + hd) * HW + p) * 4 + (c & 3)] = acc;
        }
    }
}

// ---------------- kernel B: 11x11 stride-8 pad-2 conv + exact GELU ----------------
// grid: 2 tensors * 2 b * 64 oc = 256 blocks, 256 threads (8 warps, pos warp-strided)
__global__ void conv_kernel(const float* __restrict__ wq, const float* __restrict__ bq,
                            const float* __restrict__ wk, const float* __restrict__ bk) {
    int bid = blockIdx.x;
    int t  = bid >> 7;
    int b  = (bid >> 6) & 1;
    int oc = bid & 63;

    const float* wsrc = (t ? wk : wq) + oc * 64 * 121;
    const float* in   = (t ? g_kt : g_qt) + b * HW * 64;

    __shared__ float sw[121 * 64];   // [tap][ic]
    for (int idx = threadIdx.x; idx < 121 * 64; idx += 256) {
        int tap = idx >> 6, ic = idx & 63;
        sw[idx] = wsrc[ic * 121 + tap];
    }
    __syncthreads();

    int warp = threadIdx.x >> 5, lane = threadIdx.x & 31;
    for (int pos = warp; pos < 36; pos += 8) {
        int oh = pos / 6, ow = pos % 6;
        int ihb = oh * 8 - 2, iwb = ow * 8 - 2;
        float acc0 = 0.f, acc1 = 0.f;
        #pragma unroll
        for (int kh = 0; kh < 11; kh++) {
            int ih = ihb + kh;
            if ((unsigned)ih >= 48u) continue;
            #pragma unroll
            for (int kw = 0; kw < 11; kw++) {
                int iw = iwb + kw;
                if ((unsigned)iw >= 48u) continue;
                const float* ip = in + (ih * 48 + iw) * 64;
                const float* wp = sw + (kh * 11 + kw) * 64;
                acc0 = fmaf(ip[lane],      wp[lane],      acc0);
                acc1 = fmaf(ip[lane + 32], wp[lane + 32], acc1);
            }
        }
        float acc = acc0 + acc1;
        #pragma unroll
        for (int off = 16; off; off >>= 1)
            acc += __shfl_xor_sync(0xffffffffu, acc, off);
        if (lane == 0) {
            float x = acc + (t ? bk : bq)[oc];
            float g = 0.5f * x * (1.0f + erff(x * 0.7071067811865476f));
            (t ? g_kd : g_qd)[(b * 64 + oc) * MM + pos] = g;
        }
    }
}

// ---------------- kernel C: dots[b,h,i36,j36] ----------------
__global__ void dots_kernel() {
    int idx = blockIdx.x * 256 + threadIdx.x;
    if (idx >= NB * HEADS * MM * MM) return;
    int j  = idx % 36;
    int i  = (idx / 36) % 36;
    int bh = idx / (36 * 36);
    int b = bh >> 3, hd = bh & 7;
    const float* qd = g_qd + (b * 64 + hd * 8) * MM;
    const float* kd = g_kd + (b * 64 + hd * 8) * MM;
    float s = 0.f;
    #pragma unroll
    for (int c = 0; c < 8; c++) s = fmaf(qd[c * MM + i], kd[c * MM + j], s);
    g_dots[idx] = s * SCALE;
}

// ---------------- kernel D: fused pos-logits + softmax + attn@v ----------------
// one warp per 4 consecutive output rows (same b,head, same D-row since i0%4==0)
// grid: 36864/4/8 = 1152 blocks, 256 threads

#define FMA2(d, a, b, c) asm("fma.rn.f32x2 %0, %1, %2, %3;" : "=l"(d) : "l"(a), "l"(b), "l"(c))
#define PACK2(out, x)    asm("mov.b64 %0, {%1, %1};" : "=l"(out) : "r"(x))
#define UNPK2(lo, hi, in) asm("mov.b64 {%0, %1}, %2;" : "=r"(lo), "=r"(hi) : "l"(in))

__global__ void attn_kernel(const float* __restrict__ pos_h, const float* __restrict__ pos_w,
                            float* __restrict__ out) {
    // per warp: sD[40] (exp'd), sA[4][48], sB[4][48] (exp'd), sQ[32]
    __shared__ float sh[8][472];
    int warp = threadIdx.x >> 5, lane = threadIdx.x & 31;
    int w = blockIdx.x * 8 + warp;              // global warp id < 9216
    int bh = w / 576;                           // 2304/4 = 576 row-groups per (b,h)
    int i0 = (w % 576) * 4;
    int b = bh >> 3, hd = bh & 7;

    float* sD = sh[warp];          // 40
    float* sA = sh[warp] + 40;     // 4*48
    float* sB = sh[warp] + 232;    // 4*48
    float* sQ = sh[warp] + 424;    // 4 rows * 8 ch

    // stage q for 4 rows
    {
        int r = lane >> 3, c = lane & 7;
        sQ[lane] = g_qt[((size_t)(b * HW + i0 + r)) * 64 + hd * 8 + c];
    }
    // raw D row
    {
        const float* dsrc = g_dots + ((b * HEADS + hd) * MM + (i0 >> 6)) * MM;
        for (int t = lane; t < 36; t += 32) sD[t] = dsrc[t];
    }
    __syncwarp();

    // raw A/B for 4 rows
    for (int jh = lane; jh < 48; jh += 32) {
        #pragma unroll
        for (int r = 0; r < 4; r++) {
            float a = 0.f, bb = 0.f;
            #pragma unroll
            for (int c = 0; c < 8; c++) {
                float qv = sQ[r * 8 + c];
                a  = fmaf(qv, __ldg(&pos_h[c * 48 + jh]), a);
                bb = fmaf(qv, __ldg(&pos_w[c * 48 + jh]), bb);
            }
            sA[r * 48 + jh] = a;
            sB[r * 48 + jh] = bb;
        }
    }
    __syncwarp();

    // per-component maxes
    float mA[4], mB[4], mD = -1e30f;
    #pragma unroll
    for (int r = 0; r < 4; r++) { mA[r] = -1e30f; mB[r] = -1e30f; }
    for (int t = lane; t < 48; t += 32) {
        #pragma unroll
        for (int r = 0; r < 4; r++) {
            mA[r] = fmaxf(mA[r], sA[r * 48 + t]);
            mB[r] = fmaxf(mB[r], sB[r * 48 + t]);
        }
    }
    for (int t = lane; t < 36; t += 32) mD = fmaxf(mD, sD[t]);
    #pragma unroll
    for (int off = 16; off; off >>= 1) {
        mD = fmaxf(mD, __shfl_xor_sync(0xffffffffu, mD, off));
        #pragma unroll
        for (int r = 0; r < 4; r++) {
            mA[r] = fmaxf(mA[r], __shfl_xor_sync(0xffffffffu, mA[r], off));
            mB[r] = fmaxf(mB[r], __shfl_xor_sync(0xffffffffu, mB[r], off));
        }
    }
    __syncwarp();

    // exponentiate components in place
    for (int t = lane; t < 36; t += 32) sD[t] = __expf(sD[t] - mD);
    for (int t = lane; t < 48; t += 32) {
        #pragma unroll
        for (int r = 0; r < 4; r++) {
            sA[r * 48 + t] = __expf(sA[r * 48 + t] - mA[r]);
            sB[r * 48 + t] = __expf(sB[r * 48 + t] - mB[r]);
        }
    }
    __syncwarp();

    const ulonglong2* vlo = (const ulonglong2*)g_vlo4 + (size_t)(b * HEADS + hd) * HW;
    const ulonglong2* vhi = (const ulonglong2*)g_vhi4 + (size_t)(b * HEADS + hd) * HW;

    unsigned long long acc[4][4];
    float ssum[4];
    #pragma unroll
    for (int r = 0; r < 4; r++) {
        ssum[r] = 0.f;
        #pragma unroll
        for (int k = 0; k < 4; k++) acc[r][k] = 0ull;
    }

    int jh = 0, jw = lane;
    for (int j = lane; j < HW; j += 32) {
        float eDv = sD[j >> 6];
        ulonglong2 L = vlo[j];
        ulonglong2 H = vhi[j];
        #pragma unroll
        for (int r = 0; r < 4; r++) {
            float tt = eDv * sA[r * 48 + jh];
            float p  = tt * sB[r * 48 + jw];
            ssum[r] += p;
            unsigned long long pp;
            PACK2(pp, __float_as_uint(p));
            FMA2(acc[r][0], pp, L.x, acc[r][0]);
            FMA2(acc[r][1], pp, L.y, acc[r][1]);
            FMA2(acc[r][2], pp, H.x, acc[r][2]);
            FMA2(acc[r][3], pp, H.y, acc[r][3]);
        }
        jw += 32;
        if (jw >= 48) { jw -= 48; jh++; }
    }

    // reduce + write 4 rows
    #pragma unroll
    for (int r = 0; r < 4; r++) {
        float f0, f1, f2, f3, f4, f5, f6, f7;
        unsigned u0, u1;
        UNPK2(u0, u1, acc[r][0]); f0 = __uint_as_float(u0); f1 = __uint_as_float(u1);
        UNPK2(u0, u1, acc[r][1]); f2 = __uint_as_float(u0); f3 = __uint_as_float(u1);
        UNPK2(u0, u1, acc[r][2]); f4 = __uint_as_float(u0); f5 = __uint_as_float(u1);
        UNPK2(u0, u1, acc[r][3]); f6 = __uint_as_float(u0); f7 = __uint_as_float(u1);
        float s = ssum[r];
        #pragma unroll
        for (int off = 16; off; off >>= 1) {
            s  += __shfl_xor_sync(0xffffffffu, s, off);
            f0 += __shfl_xor_sync(0xffffffffu, f0, off);
            f1 += __shfl_xor_sync(0xffffffffu, f1, off);
            f2 += __shfl_xor_sync(0xffffffffu, f2, off);
            f3 += __shfl_xor_sync(0xffffffffu, f3, off);
            f4 += __shfl_xor_sync(0xffffffffu, f4, off);
            f5 += __shfl_xor_sync(0xffffffffu, f5, off);
            f6 += __shfl_xor_sync(0xffffffffu, f6, off);
            f7 += __shfl_xor_sync(0xffffffffu, f7, off);
        }
        float rr = f0;
        if (lane == 1) rr = f1;
        if (lane == 2) rr = f2;
        if (lane == 3) rr = f3;
        if (lane == 4) rr = f4;
        if (lane == 5) rr = f5;
        if (lane == 6) rr = f6;
        if (lane == 7) rr = f7;
        if (lane < 8)
            out[((size_t)(b * 64) + hd * 8 + lane) * HW + i0 + r] = rr / s;
    }
}

// ---------------- launch ----------------
extern "C" void kernel_launch(void* const* d_in, const int* in_sizes, int n_in,
                              void* d_out, int out_size) {
    const float* f    = (const float*)d_in[0];
    const float* wqkv = (const float*)d_in[1];
    const float* wq   = (const float*)d_in[2];
    const float* bq   = (const float*)d_in[3];
    const float* wk   = (const float*)d_in[4];
    const float* bk   = (const float*)d_in[5];
    const float* ph   = (const float*)d_in[6];
    const float* pw   = (const float*)d_in[7];
    float* out = (float*)d_out;

    qkv_kernel<<<72, 256>>>(f, wqkv);
    conv_kernel<<<256, 256>>>(wq, bq, wk, bk);
    dots_kernel<<<81, 256>>>();
    attn_kernel<<<1152, 256>>>(ph, pw, out);
}

// round 4
// speedup vs baseline: 3.4427x; 1.0264x over previous
#include <cuda_runtime.h>
#include <math.h>
#include <stdint.h>

#define NB 2
#define NC 64
#define HW 2304
#define INNER 64
#define HEADS 8
#define DH 8
#define MM 36
#define SCALE 0.35355339059327373f

// ---------------- scratch (device globals; no allocation allowed) ----------------
__device__ float g_qt[NB * HW * INNER];          // q channel-last: [b][p][c]
__device__ float g_kt[NB * HW * INNER];          // k channel-last: [b][p][c]
__device__ float4 g_vlo4[NB * HEADS * HW];       // v channels 0..3:  [b][head][j]
__device__ float4 g_vhi4[NB * HEADS * HW];       // v channels 4..7
__device__ float g_qd[NB * INNER * MM];          // conv+gelu(q): [b][oc][pos36]
__device__ float g_kd[NB * INNER * MM];
__device__ float g_dots[NB * HEADS * MM * MM];   // [b][head][i36][j36]

// ---------------- kernel A: 1x1 conv qkv + layout transforms ----------------
// grid: 2 b * 72 ptiles(32) = 144 blocks, 256 threads
__global__ void qkv_kernel(const float* __restrict__ f, const float* __restrict__ wqkv) {
    __shared__ float sF[64 * 32];   // [c][pp]
    int b = blockIdx.x / 72;
    int p0 = (blockIdx.x % 72) * 32;

    for (int idx = threadIdx.x; idx < 64 * 32; idx += 256) {
        int c = idx >> 5, pp = idx & 31;
        sF[idx] = f[(b * 64 + c) * HW + p0 + pp];
    }
    __syncthreads();

    int pp = threadIdx.x & 31;
    int o0 = threadIdx.x >> 5;   // 0..7
    int p = p0 + pp;
    for (int o = o0; o < 192; o += 8) {
        const float* wr = wqkv + o * 64;
        float a0 = 0.f, a1 = 0.f, a2 = 0.f, a3 = 0.f;
        #pragma unroll
        for (int c = 0; c < 16; c++) {
            a0 = fmaf(__ldg(&wr[c]),      sF[c * 32 + pp],        a0);
            a1 = fmaf(__ldg(&wr[c + 16]), sF[(c + 16) * 32 + pp], a1);
            a2 = fmaf(__ldg(&wr[c + 32]), sF[(c + 32) * 32 + pp], a2);
            a3 = fmaf(__ldg(&wr[c + 48]), sF[(c + 48) * 32 + pp], a3);
        }
        float acc = (a0 + a1) + (a2 + a3);
        if (o < 64) {
            g_qt[(b * HW + p) * 64 + o] = acc;
        } else if (o < 128) {
            g_kt[(b * HW + p) * 64 + (o - 64)] = acc;
        } else {
            int oi = o - 128;
            int hd = oi >> 3, c = oi & 7;
            float* vout = (float*)(c < 4 ? g_vlo4 : g_vhi4);
            vout[((size_t)(b * HEADS + hd) * HW + p) * 4 + (c & 3)] = acc;
        }
    }
}

// ---------------- kernel B: 11x11 stride-8 pad-2 conv + exact GELU ----------------
// grid: 2 tensors * 2 b * 64 oc * 2 pos-halves = 512 blocks, 288 threads (9 warps, 2 pos each)
__global__ void conv_kernel(const float* __restrict__ wq, const float* __restrict__ bq,
                            const float* __restrict__ wk, const float* __restrict__ bk) {
    int bid = blockIdx.x;
    int half = bid & 1;
    int oc = (bid >> 1) & 63;
    int b  = (bid >> 7) & 1;
    int t  = bid >> 8;

    const float* wsrc = (t ? wk : wq) + oc * 64 * 121;   // layout [ic][tap], linear
    const float* in   = (t ? g_kt : g_qt) + b * HW * 64;

    __shared__ float sw[121 * 65];   // [tap][ic], pad 65 for conflict-free transpose
    for (int idx = threadIdx.x; idx < 121 * 64; idx += 288) {
        int ic = idx / 121, tap = idx % 121;
        sw[tap * 65 + ic] = wsrc[idx];                   // coalesced LDG, conflict-free STS
    }
    __syncthreads();

    int warp = threadIdx.x >> 5, lane = threadIdx.x & 31;
    int pos0 = half * 18 + warp * 2;

    int oh0 = pos0 / 6, ow0 = pos0 % 6;
    int oh1 = (pos0 + 1) / 6, ow1 = (pos0 + 1) % 6;
    int ihb0 = oh0 * 8 - 2, iwb0 = ow0 * 8 - 2;
    int ihb1 = oh1 * 8 - 2, iwb1 = ow1 * 8 - 2;

    float p0a = 0.f, p0b = 0.f, p1a = 0.f, p1b = 0.f;
    #pragma unroll
    for (int kh = 0; kh < 11; kh++) {
        #pragma unroll
        for (int kw = 0; kw < 11; kw++) {
            const float* wp = sw + (kh * 11 + kw) * 65;
            float w0 = wp[lane], w1 = wp[lane + 32];
            int ih0 = ihb0 + kh, iw0 = iwb0 + kw;
            if ((unsigned)ih0 < 48u && (unsigned)iw0 < 48u) {
                const float* ip = in + (ih0 * 48 + iw0) * 64;
                p0a = fmaf(ip[lane], w0, p0a);
                p0b = fmaf(ip[lane + 32], w1, p0b);
            }
            int ih1 = ihb1 + kh, iw1 = iwb1 + kw;
            if ((unsigned)ih1 < 48u && (unsigned)iw1 < 48u) {
                const float* ip = in + (ih1 * 48 + iw1) * 64;
                p1a = fmaf(ip[lane], w0, p1a);
                p1b = fmaf(ip[lane + 32], w1, p1b);
            }
        }
    }
    float acc0 = p0a + p0b;
    float acc1 = p1a + p1b;
    #pragma unroll
    for (int off = 16; off; off >>= 1) {
        acc0 += __shfl_xor_sync(0xffffffffu, acc0, off);
        acc1 += __shfl_xor_sync(0xffffffffu, acc1, off);
    }
    if (lane == 0) {
        float bias = (t ? bk : bq)[oc];
        float* dst = (t ? g_kd : g_qd) + (b * 64 + oc) * MM;
        float x0 = acc0 + bias;
        dst[pos0] = 0.5f * x0 * (1.0f + erff(x0 * 0.7071067811865476f));
        float x1 = acc1 + bias;
        dst[pos0 + 1] = 0.5f * x1 * (1.0f + erff(x1 * 0.7071067811865476f));
    }
}

// ---------------- kernel C: dots[b,h,i36,j36] ----------------
__global__ void dots_kernel() {
    int idx = blockIdx.x * 256 + threadIdx.x;
    if (idx >= NB * HEADS * MM * MM) return;
    int j  = idx % 36;
    int i  = (idx / 36) % 36;
    int bh = idx / (36 * 36);
    int b = bh >> 3, hd = bh & 7;
    const float* qd = g_qd + (b * 64 + hd * 8) * MM;
    const float* kd = g_kd + (b * 64 + hd * 8) * MM;
    float s = 0.f;
    #pragma unroll
    for (int c = 0; c < 8; c++) s = fmaf(qd[c * MM + i], kd[c * MM + j], s);
    g_dots[idx] = s * SCALE;
}

// ---------------- kernel D: fused pos-logits + softmax + attn@v ----------------
// one warp per 4 consecutive output rows; grid 1152 blocks, 256 threads

#define FMA2(d, a, b, c) asm("fma.rn.f32x2 %0, %1, %2, %3;" : "=l"(d) : "l"(a), "l"(b), "l"(c))
#define PACK2(out, x)    asm("mov.b64 %0, {%1, %1};" : "=l"(out) : "r"(x))
#define UNPK2(lo, hi, in) asm("mov.b64 {%0, %1}, %2;" : "=r"(lo), "=r"(hi) : "l"(in))

// per-warp smem floats: sQ 32 | sD 36(+4) | sA 192 | sB 192 | eC 576  = 1032
#define WSH 1032

__global__ void attn_kernel(const float* __restrict__ pos_h, const float* __restrict__ pos_w,
                            float* __restrict__ out) {
    __shared__ float sh[8][WSH];
    int warp = threadIdx.x >> 5, lane = threadIdx.x & 31;
    int w = blockIdx.x * 8 + warp;              // global warp id < 9216
    int bh = w / 576;                           // 2304/4 = 576 row-groups per (b,h)
    int i0 = (w % 576) * 4;
    int b = bh >> 3, hd = bh & 7;

    float* sQ = sh[warp];          // 32
    float* sD = sh[warp] + 32;     // 40
    float* sA = sh[warp] + 72;     // 4*48
    float* sB = sh[warp] + 264;    // 4*48
    float* eC = sh[warp] + 456;    // 4*144

    // stage q for 4 rows
    {
        int r = lane >> 3, c = lane & 7;
        sQ[lane] = g_qt[((size_t)(b * HW + i0 + r)) * 64 + hd * 8 + c];
    }
    // raw D row
    {
        const float* dsrc = g_dots + ((b * HEADS + hd) * MM + (i0 >> 6)) * MM;
        for (int t = lane; t < 36; t += 32) sD[t] = dsrc[t];
    }
    __syncwarp();

    // raw A/B for 4 rows
    for (int jh = lane; jh < 48; jh += 32) {
        #pragma unroll
        for (int r = 0; r < 4; r++) {
            float a = 0.f, bb = 0.f;
            #pragma unroll
            for (int c = 0; c < 8; c++) {
                float qv = sQ[r * 8 + c];
                a  = fmaf(qv, __ldg(&pos_h[c * 48 + jh]), a);
                bb = fmaf(qv, __ldg(&pos_w[c * 48 + jh]), bb);
            }
            sA[r * 48 + jh] = a;
            sB[r * 48 + jh] = bb;
        }
    }
    __syncwarp();

    // per-component maxes
    float mA[4], mB[4], mD = -1e30f;
    #pragma unroll
    for (int r = 0; r < 4; r++) { mA[r] = -1e30f; mB[r] = -1e30f; }
    for (int t = lane; t < 48; t += 32) {
        #pragma unroll
        for (int r = 0; r < 4; r++) {
            mA[r] = fmaxf(mA[r], sA[r * 48 + t]);
            mB[r] = fmaxf(mB[r], sB[r * 48 + t]);
        }
    }
    for (int t = lane; t < 36; t += 32) mD = fmaxf(mD, sD[t]);
    #pragma unroll
    for (int off = 16; off; off >>= 1) {
        mD = fmaxf(mD, __shfl_xor_sync(0xffffffffu, mD, off));
        #pragma unroll
        for (int r = 0; r < 4; r++) {
            mA[r] = fmaxf(mA[r], __shfl_xor_sync(0xffffffffu, mA[r], off));
            mB[r] = fmaxf(mB[r], __shfl_xor_sync(0xffffffffu, mB[r], off));
        }
    }
    __syncwarp();

    // exponentiate components in place
    for (int t = lane; t < 36; t += 32) sD[t] = __expf(sD[t] - mD);
    for (int t = lane; t < 48; t += 32) {
        #pragma unroll
        for (int r = 0; r < 4; r++) {
            sA[r * 48 + t] = __expf(sA[r * 48 + t] - mA[r]);
            sB[r * 48 + t] = __expf(sB[r * 48 + t] - mB[r]);
        }
    }
    __syncwarp();

    // combined table: within each 16-aligned j segment s=j>>4, both j/48 and j>>6 constant
    for (int s = lane; s < 144; s += 32) {
        float d = sD[s >> 2];
        int jh = s / 3;
        #pragma unroll
        for (int r = 0; r < 4; r++)
            eC[r * 144 + s] = sA[r * 48 + jh] * d;
    }
    __syncwarp();

    const ulonglong2* vlo = (const ulonglong2*)g_vlo4 + (size_t)(b * HEADS + hd) * HW;
    const ulonglong2* vhi = (const ulonglong2*)g_vhi4 + (size_t)(b * HEADS + hd) * HW;

    unsigned long long acc[4][4];
    float ssum[4];
    #pragma unroll
    for (int r = 0; r < 4; r++) {
        ssum[r] = 0.f;
        #pragma unroll
        for (int k = 0; k < 4; k++) acc[r][k] = 0ull;
    }

    int s = lane >> 4;     // j>>4 for this lane; advances by 2 each iter (j += 32)
    int jw = lane;         // j % 48
    for (int j = lane; j < HW; j += 32) {
        ulonglong2 L = vlo[j];
        ulonglong2 H = vhi[j];
        #pragma unroll
        for (int r = 0; r < 4; r++) {
            float p = eC[r * 144 + s] * sB[r * 48 + jw];
            ssum[r] += p;
            unsigned long long pp;
            PACK2(pp, __float_as_uint(p));
            FMA2(acc[r][0], pp, L.x, acc[r][0]);
            FMA2(acc[r][1], pp, L.y, acc[r][1]);
            FMA2(acc[r][2], pp, H.x, acc[r][2]);
            FMA2(acc[r][3], pp, H.y, acc[r][3]);
        }
        s += 2;
        jw += 32;
        if (jw >= 48) jw -= 48;
    }

    // reduce + write 4 rows
    #pragma unroll
    for (int r = 0; r < 4; r++) {
        float f0, f1, f2, f3, f4, f5, f6, f7;
        unsigned u0, u1;
        UNPK2(u0, u1, acc[r][0]); f0 = __uint_as_float(u0); f1 = __uint_as_float(u1);
        UNPK2(u0, u1, acc[r][1]); f2 = __uint_as_float(u0); f3 = __uint_as_float(u1);
        UNPK2(u0, u1, acc[r][2]); f4 = __uint_as_float(u0); f5 = __uint_as_float(u1);
        UNPK2(u0, u1, acc[r][3]); f6 = __uint_as_float(u0); f7 = __uint_as_float(u1);
        float sv = ssum[r];
        #pragma unroll
        for (int off = 16; off; off >>= 1) {
            sv += __shfl_xor_sync(0xffffffffu, sv, off);
            f0 += __shfl_xor_sync(0xffffffffu, f0, off);
            f1 += __shfl_xor_sync(0xffffffffu, f1, off);
            f2 += __shfl_xor_sync(0xffffffffu, f2, off);
            f3 += __shfl_xor_sync(0xffffffffu, f3, off);
            f4 += __shfl_xor_sync(0xffffffffu, f4, off);
            f5 += __shfl_xor_sync(0xffffffffu, f5, off);
            f6 += __shfl_xor_sync(0xffffffffu, f6, off);
            f7 += __shfl_xor_sync(0xffffffffu, f7, off);
        }
        float rr = f0;
        if (lane == 1) rr = f1;
        if (lane == 2) rr = f2;
        if (lane == 3) rr = f3;
        if (lane == 4) rr = f4;
        if (lane == 5) rr = f5;
        if (lane == 6) rr = f6;
        if (lane == 7) rr = f7;
        if (lane < 8)
            out[((size_t)(b * 64) + hd * 8 + lane) * HW + i0 + r] = rr / sv;
    }
}

// ---------------- launch ----------------
extern "C" void kernel_launch(void* const* d_in, const int* in_sizes, int n_in,
                              void* d_out, int out_size) {
    const float* f    = (const float*)d_in[0];
    const float* wqkv = (const float*)d_in[1];
    const float* wq   = (const float*)d_in[2];
    const float* bq   = (const float*)d_in[3];
    const float* wk   = (const float*)d_in[4];
    const float* bk   = (const float*)d_in[5];
    const float* ph   = (const float*)d_in[6];
    const float* pw   = (const float*)d_in[7];
    float* out = (float*)d_out;

    qkv_kernel<<<144, 256>>>(f, wqkv);
    conv_kernel<<<512, 288>>>(wq, bq, wk, bk);
    dots_kernel<<<81, 256>>>();
    attn_kernel<<<1152, 256>>>(ph, pw, out);
}

// round 5
// speedup vs baseline: 4.1429x; 1.2034x over previous
#include <cuda_runtime.h>
#include <math.h>
#include <stdint.h>

#define NB 2
#define NC 64
#define HW 2304
#define INNER 64
#define HEADS 8
#define DH 8
#define MM 36
#define SCALE 0.35355339059327373f

// ---------------- scratch (device globals; no allocation allowed) ----------------
__device__ float g_qt[NB * HW * INNER];          // q channel-last: [b][p][c]
__device__ float g_kt[NB * HW * INNER];          // k channel-last: [b][p][c]
__device__ float4 g_vlo4[NB * HEADS * HW];       // v channels 0..3:  [b][head][j]
__device__ float4 g_vhi4[NB * HEADS * HW];       // v channels 4..7
__device__ float g_qd[NB * INNER * MM];          // conv+gelu(q): [b][oc][pos36]
__device__ float g_kd[NB * INNER * MM];
__device__ float g_dots[NB * HEADS * MM * MM];   // [b][head][i36][j36]

// ---------------- kernel A: 1x1 conv qkv + layout transforms ----------------
__global__ void qkv_kernel(const float* __restrict__ f, const float* __restrict__ wqkv) {
    __shared__ float sF[64 * 32];   // [c][pp]
    int b = blockIdx.x / 72;
    int p0 = (blockIdx.x % 72) * 32;

    for (int idx = threadIdx.x; idx < 64 * 32; idx += 256) {
        int c = idx >> 5, pp = idx & 31;
        sF[idx] = f[(b * 64 + c) * HW + p0 + pp];
    }
    __syncthreads();

    int pp = threadIdx.x & 31;
    int o0 = threadIdx.x >> 5;   // 0..7
    int p = p0 + pp;
    for (int o = o0; o < 192; o += 8) {
        const float* wr = wqkv + o * 64;
        float a0 = 0.f, a1 = 0.f, a2 = 0.f, a3 = 0.f;
        #pragma unroll
        for (int c = 0; c < 16; c++) {
            a0 = fmaf(__ldg(&wr[c]),      sF[c * 32 + pp],        a0);
            a1 = fmaf(__ldg(&wr[c + 16]), sF[(c + 16) * 32 + pp], a1);
            a2 = fmaf(__ldg(&wr[c + 32]), sF[(c + 32) * 32 + pp], a2);
            a3 = fmaf(__ldg(&wr[c + 48]), sF[(c + 48) * 32 + pp], a3);
        }
        float acc = (a0 + a1) + (a2 + a3);
        if (o < 64) {
            g_qt[(b * HW + p) * 64 + o] = acc;
        } else if (o < 128) {
            g_kt[(b * HW + p) * 64 + (o - 64)] = acc;
        } else {
            int oi = o - 128;
            int hd = oi >> 3, c = oi & 7;
            float* vout = (float*)(c < 4 ? g_vlo4 : g_vhi4);
            vout[((size_t)(b * HEADS + hd) * HW + p) * 4 + (c & 3)] = acc;
        }
    }
}

// ---------------- kernel B: 11x11 stride-8 pad-2 conv + exact GELU ----------------
__global__ void conv_kernel(const float* __restrict__ wq, const float* __restrict__ bq,
                            const float* __restrict__ wk, const float* __restrict__ bk) {
    int bid = blockIdx.x;
    int half = bid & 1;
    int oc = (bid >> 1) & 63;
    int b  = (bid >> 7) & 1;
    int t  = bid >> 8;

    const float* wsrc = (t ? wk : wq) + oc * 64 * 121;   // layout [ic][tap], linear
    const float* in   = (t ? g_kt : g_qt) + b * HW * 64;

    __shared__ float sw[121 * 65];
    for (int idx = threadIdx.x; idx < 121 * 64; idx += 288) {
        int ic = idx / 121, tap = idx % 121;
        sw[tap * 65 + ic] = wsrc[idx];
    }
    __syncthreads();

    int warp = threadIdx.x >> 5, lane = threadIdx.x & 31;
    int pos0 = half * 18 + warp * 2;

    int oh0 = pos0 / 6, ow0 = pos0 % 6;
    int oh1 = (pos0 + 1) / 6, ow1 = (pos0 + 1) % 6;
    int ihb0 = oh0 * 8 - 2, iwb0 = ow0 * 8 - 2;
    int ihb1 = oh1 * 8 - 2, iwb1 = ow1 * 8 - 2;

    float p0a = 0.f, p0b = 0.f, p1a = 0.f, p1b = 0.f;
    #pragma unroll
    for (int kh = 0; kh < 11; kh++) {
        #pragma unroll
        for (int kw = 0; kw < 11; kw++) {
            const float* wp = sw + (kh * 11 + kw) * 65;
            float w0 = wp[lane], w1 = wp[lane + 32];
            int ih0 = ihb0 + kh, iw0 = iwb0 + kw;
            if ((unsigned)ih0 < 48u && (unsigned)iw0 < 48u) {
                const float* ip = in + (ih0 * 48 + iw0) * 64;
                p0a = fmaf(ip[lane], w0, p0a);
                p0b = fmaf(ip[lane + 32], w1, p0b);
            }
            int ih1 = ihb1 + kh, iw1 = iwb1 + kw;
            if ((unsigned)ih1 < 48u && (unsigned)iw1 < 48u) {
                const float* ip = in + (ih1 * 48 + iw1) * 64;
                p1a = fmaf(ip[lane], w0, p1a);
                p1b = fmaf(ip[lane + 32], w1, p1b);
            }
        }
    }
    float acc0 = p0a + p0b;
    float acc1 = p1a + p1b;
    #pragma unroll
    for (int off = 16; off; off >>= 1) {
        acc0 += __shfl_xor_sync(0xffffffffu, acc0, off);
        acc1 += __shfl_xor_sync(0xffffffffu, acc1, off);
    }
    if (lane == 0) {
        float bias = (t ? bk : bq)[oc];
        float* dst = (t ? g_kd : g_qd) + (b * 64 + oc) * MM;
        float x0 = acc0 + bias;
        dst[pos0] = 0.5f * x0 * (1.0f + erff(x0 * 0.7071067811865476f));
        float x1 = acc1 + bias;
        dst[pos0 + 1] = 0.5f * x1 * (1.0f + erff(x1 * 0.7071067811865476f));
    }
}

// ---------------- kernel C: dots[b,h,i36,j36] ----------------
__global__ void dots_kernel() {
    int idx = blockIdx.x * 256 + threadIdx.x;
    if (idx >= NB * HEADS * MM * MM) return;
    int j  = idx % 36;
    int i  = (idx / 36) % 36;
    int bh = idx / (36 * 36);
    int b = bh >> 3, hd = bh & 7;
    const float* qd = g_qd + (b * 64 + hd * 8) * MM;
    const float* kd = g_kd + (b * 64 + hd * 8) * MM;
    float s = 0.f;
    #pragma unroll
    for (int c = 0; c < 8; c++) s = fmaf(qd[c * MM + i], kd[c * MM + j], s);
    g_dots[idx] = s * SCALE;
}

// ---------------- kernel D: fused pos-logits + softmax + attn@v ----------------
// one warp per 4 consecutive output rows; grid 1152 blocks, 256 threads

#define FMA2(d, a, b, c) asm("fma.rn.f32x2 %0, %1, %2, %3;" : "=l"(d) : "l"(a), "l"(b), "l"(c))
#define PACK2(out, x)    asm("mov.b64 %0, {%1, %1};" : "=l"(out) : "r"(x))
#define UNPK2(lo, hi, in) asm("mov.b64 {%0, %1}, %2;" : "=r"(lo), "=r"(hi) : "l"(in))

// per-warp smem floats: sQ 32 | sD 40 | sA 192 | sB 192 | eC2 576 = 1032
// sB2[48][4] aliases the sA region after eC2 is built.
#define WSH 1032

__global__ void __launch_bounds__(256, 3)
attn_kernel(const float* __restrict__ pos_h, const float* __restrict__ pos_w,
            float* __restrict__ out) {
    __shared__ float sh[8][WSH];
    int warp = threadIdx.x >> 5, lane = threadIdx.x & 31;
    int w = blockIdx.x * 8 + warp;              // global warp id < 9216
    int bh = w / 576;
    int i0 = (w % 576) * 4;
    int b = bh >> 3, hd = bh & 7;

    float* sQ  = sh[warp];          // 32
    float* sD  = sh[warp] + 32;     // 40  (later reused as sumB16[12])
    float* sA  = sh[warp] + 72;     // 4*48
    float* sB  = sh[warp] + 264;    // 4*48
    float* eC2 = sh[warp] + 456;    // 144*4, layout [s][r]
    float* sB2 = sh[warp] + 72;     // alias sA: [w][r]
    float* smB = sh[warp] + 32;     // alias sD: sumB16[r*3+phi]

    // stage q for 4 rows
    {
        int r = lane >> 3, c = lane & 7;
        sQ[lane] = g_qt[((size_t)(b * HW + i0 + r)) * 64 + hd * 8 + c];
    }
    // raw D row
    {
        const float* dsrc = g_dots + ((b * HEADS + hd) * MM + (i0 >> 6)) * MM;
        for (int t = lane; t < 36; t += 32) sD[t] = dsrc[t];
    }
    __syncwarp();

    // raw A/B for 4 rows
    for (int jh = lane; jh < 48; jh += 32) {
        #pragma unroll
        for (int r = 0; r < 4; r++) {
            float a = 0.f, bb = 0.f;
            #pragma unroll
            for (int c = 0; c < 8; c++) {
                float qv = sQ[r * 8 + c];
                a  = fmaf(qv, __ldg(&pos_h[c * 48 + jh]), a);
                bb = fmaf(qv, __ldg(&pos_w[c * 48 + jh]), bb);
            }
            sA[r * 48 + jh] = a;
            sB[r * 48 + jh] = bb;
        }
    }
    __syncwarp();

    // per-component maxes
    float mA[4], mB[4], mD = -1e30f;
    #pragma unroll
    for (int r = 0; r < 4; r++) { mA[r] = -1e30f; mB[r] = -1e30f; }
    for (int t = lane; t < 48; t += 32) {
        #pragma unroll
        for (int r = 0; r < 4; r++) {
            mA[r] = fmaxf(mA[r], sA[r * 48 + t]);
            mB[r] = fmaxf(mB[r], sB[r * 48 + t]);
        }
    }
    for (int t = lane; t < 36; t += 32) mD = fmaxf(mD, sD[t]);
    #pragma unroll
    for (int off = 16; off; off >>= 1) {
        mD = fmaxf(mD, __shfl_xor_sync(0xffffffffu, mD, off));
        #pragma unroll
        for (int r = 0; r < 4; r++) {
            mA[r] = fmaxf(mA[r], __shfl_xor_sync(0xffffffffu, mA[r], off));
            mB[r] = fmaxf(mB[r], __shfl_xor_sync(0xffffffffu, mB[r], off));
        }
    }
    __syncwarp();

    // exponentiate components in place
    for (int t = lane; t < 36; t += 32) sD[t] = __expf(sD[t] - mD);
    for (int t = lane; t < 48; t += 32) {
        #pragma unroll
        for (int r = 0; r < 4; r++) {
            sA[r * 48 + t] = __expf(sA[r * 48 + t] - mA[r]);
            sB[r * 48 + t] = __expf(sB[r * 48 + t] - mB[r]);
        }
    }
    __syncwarp();

    // eC2[s][r] = eA[r][s/3] * eD[s>>2]   (s = j>>4; 16-segments align with both maps)
    for (int s = lane; s < 144; s += 32) {
        float d = sD[s >> 2];
        int jh = s / 3;
        float4 v;
        v.x = sA[0 * 48 + jh] * d;
        v.y = sA[1 * 48 + jh] * d;
        v.z = sA[2 * 48 + jh] * d;
        v.w = sA[3 * 48 + jh] * d;
        *(float4*)&eC2[s * 4] = v;
    }
    __syncwarp();

    // sumB16[r][phi] = sum_{u<16} eB[r][16*phi+u]  (into sD region; sD dead now)
    if (lane < 12) {
        int r = lane >> 2;        // wrong split would be lane/3; use mapping below
    }
    // map lane 0..11 -> (r = lane/3, phi = lane%3)
    if (lane < 12) {
        int r = lane / 3, phi = lane % 3;
        float s16 = 0.f;
        #pragma unroll
        for (int u = 0; u < 16; u++) s16 += sB[r * 48 + phi * 16 + u];
        smB[r * 3 + phi] = s16;
    }
    __syncwarp();

    // sB2[w][r] = eB[r][w]  (overwrites sA region — safe, eC2 already built)
    for (int t = lane; t < 48; t += 32) {
        float4 v;
        v.x = sB[0 * 48 + t];
        v.y = sB[1 * 48 + t];
        v.z = sB[2 * 48 + t];
        v.w = sB[3 * 48 + t];
        *(float4*)&sB2[t * 4] = v;
    }
    __syncwarp();

    // per-lane partial row sums: ssum[r] = sum_s eC2[s][r] * sumB16[r][s%3]
    float ssum[4] = {0.f, 0.f, 0.f, 0.f};
    for (int s = lane; s < 144; s += 32) {
        int phi = s % 3;
        float4 c = *(const float4*)&eC2[s * 4];
        ssum[0] = fmaf(c.x, smB[0 + phi], ssum[0]);
        ssum[1] = fmaf(c.y, smB[3 + phi], ssum[1]);
        ssum[2] = fmaf(c.z, smB[6 + phi], ssum[2]);
        ssum[3] = fmaf(c.w, smB[9 + phi], ssum[3]);
    }

    const ulonglong2* vlo = (const ulonglong2*)g_vlo4 + (size_t)(b * HEADS + hd) * HW;
    const ulonglong2* vhi = (const ulonglong2*)g_vhi4 + (size_t)(b * HEADS + hd) * HW;

    unsigned long long acc[4][4];
    #pragma unroll
    for (int r = 0; r < 4; r++)
        #pragma unroll
        for (int k = 0; k < 4; k++) acc[r][k] = 0ull;

    int j = lane;
    int s1 = lane >> 4;                       // j>>4; partner j+32 -> s1+2
    int jw1 = lane;                           // j % 48 (lane < 48)
    int jw2 = (lane >= 16) ? lane - 16 : lane + 32;   // (j+32) % 48

    #pragma unroll 1
    for (int t = 0; t < 36; t++) {
        ulonglong2 La = vlo[j],      Ha = vhi[j];
        ulonglong2 Lb = vlo[j + 32], Hb = vhi[j + 32];
        float4 c1 = *(const float4*)&eC2[s1 * 4];
        float4 c2 = *(const float4*)&eC2[(s1 + 2) * 4];
        float4 b1 = *(const float4*)&sB2[jw1 * 4];
        float4 b2 = *(const float4*)&sB2[jw2 * 4];

        float pa0 = c1.x * b1.x, pb0 = c2.x * b2.x;
        float pa1 = c1.y * b1.y, pb1 = c2.y * b2.y;
        float pa2 = c1.z * b1.z, pb2 = c2.z * b2.z;
        float pa3 = c1.w * b1.w, pb3 = c2.w * b2.w;

        unsigned long long qa0, qa1, qa2, qa3, qb0, qb1, qb2, qb3;
        PACK2(qa0, __float_as_uint(pa0)); PACK2(qb0, __float_as_uint(pb0));
        PACK2(qa1, __float_as_uint(pa1)); PACK2(qb1, __float_as_uint(pb1));
        PACK2(qa2, __float_as_uint(pa2)); PACK2(qb2, __float_as_uint(pb2));
        PACK2(qa3, __float_as_uint(pa3)); PACK2(qb3, __float_as_uint(pb3));

        FMA2(acc[0][0], qa0, La.x, acc[0][0]); FMA2(acc[0][1], qa0, La.y, acc[0][1]);
        FMA2(acc[0][2], qa0, Ha.x, acc[0][2]); FMA2(acc[0][3], qa0, Ha.y, acc[0][3]);
        FMA2(acc[1][0], qa1, La.x, acc[1][0]); FMA2(acc[1][1], qa1, La.y, acc[1][1]);
        FMA2(acc[1][2], qa1, Ha.x, acc[1][2]); FMA2(acc[1][3], qa1, Ha.y, acc[1][3]);
        FMA2(acc[2][0], qa2, La.x, acc[2][0]); FMA2(acc[2][1], qa2, La.y, acc[2][1]);
        FMA2(acc[2][2], qa2, Ha.x, acc[2][2]); FMA2(acc[2][3], qa2, Ha.y, acc[2][3]);
        FMA2(acc[3][0], qa3, La.x, acc[3][0]); FMA2(acc[3][1], qa3, La.y, acc[3][1]);
        FMA2(acc[3][2], qa3, Ha.x, acc[3][2]); FMA2(acc[3][3], qa3, Ha.y, acc[3][3]);

        FMA2(acc[0][0], qb0, Lb.x, acc[0][0]); FMA2(acc[0][1], qb0, Lb.y, acc[0][1]);
        FMA2(acc[0][2], qb0, Hb.x, acc[0][2]); FMA2(acc[0][3], qb0, Hb.y, acc[0][3]);
        FMA2(acc[1][0], qb1, Lb.x, acc[1][0]); FMA2(acc[1][1], qb1, Lb.y, acc[1][1]);
        FMA2(acc[1][2], qb1, Hb.x, acc[1][2]); FMA2(acc[1][3], qb1, Hb.y, acc[1][3]);
        FMA2(acc[2][0], qb2, Lb.x, acc[2][0]); FMA2(acc[2][1], qb2, Lb.y, acc[2][1]);
        FMA2(acc[2][2], qb2, Hb.x, acc[2][2]); FMA2(acc[2][3], qb2, Hb.y, acc[2][3]);
        FMA2(acc[3][0], qb3, Lb.x, acc[3][0]); FMA2(acc[3][1], qb3, Lb.y, acc[3][1]);
        FMA2(acc[3][2], qb3, Hb.x, acc[3][2]); FMA2(acc[3][3], qb3, Hb.y, acc[3][3]);

        j += 64;
        s1 += 4;
        jw1 += 16; if (jw1 >= 48) jw1 -= 48;
        jw2 += 16; if (jw2 >= 48) jw2 -= 48;
    }

    // reduce + write 4 rows
    #pragma unroll
    for (int r = 0; r < 4; r++) {
        float f0, f1, f2, f3, f4, f5, f6, f7;
        unsigned u0, u1;
        UNPK2(u0, u1, acc[r][0]); f0 = __uint_as_float(u0); f1 = __uint_as_float(u1);
        UNPK2(u0, u1, acc[r][1]); f2 = __uint_as_float(u0); f3 = __uint_as_float(u1);
        UNPK2(u0, u1, acc[r][2]); f4 = __uint_as_float(u0); f5 = __uint_as_float(u1);
        UNPK2(u0, u1, acc[r][3]); f6 = __uint_as_float(u0); f7 = __uint_as_float(u1);
        float sv = ssum[r];
        #pragma unroll
        for (int off = 16; off; off >>= 1) {
            sv += __shfl_xor_sync(0xffffffffu, sv, off);
            f0 += __shfl_xor_sync(0xffffffffu, f0, off);
            f1 += __shfl_xor_sync(0xffffffffu, f1, off);
            f2 += __shfl_xor_sync(0xffffffffu, f2, off);
            f3 += __shfl_xor_sync(0xffffffffu, f3, off);
            f4 += __shfl_xor_sync(0xffffffffu, f4, off);
            f5 += __shfl_xor_sync(0xffffffffu, f5, off);
            f6 += __shfl_xor_sync(0xffffffffu, f6, off);
            f7 += __shfl_xor_sync(0xffffffffu, f7, off);
        }
        float rr = f0;
        if (lane == 1) rr = f1;
        if (lane == 2) rr = f2;
        if (lane == 3) rr = f3;
        if (lane == 4) rr = f4;
        if (lane == 5) rr = f5;
        if (lane == 6) rr = f6;
        if (lane == 7) rr = f7;
        if (lane < 8)
            out[((size_t)(b * 64) + hd * 8 + lane) * HW + i0 + r] = rr / sv;
    }
}

// ---------------- launch ----------------
extern "C" void kernel_launch(void* const* d_in, const int* in_sizes, int n_in,
                              void* d_out, int out_size) {
    const float* f    = (const float*)d_in[0];
    const float* wqkv = (const float*)d_in[1];
    const float* wq   = (const float*)d_in[2];
    const float* bq   = (const float*)d_in[3];
    const float* wk   = (const float*)d_in[4];
    const float* bk   = (const float*)d_in[5];
    const float* ph   = (const float*)d_in[6];
    const float* pw   = (const float*)d_in[7];
    float* out = (float*)d_out;

    qkv_kernel<<<144, 256>>>(f, wqkv);
    conv_kernel<<<512, 288>>>(wq, bq, wk, bk);
    dots_kernel<<<81, 256>>>();
    attn_kernel<<<1152, 256>>>(ph, pw, out);
}